// round 15
// baseline (speedup 1.0000x reference)
#include <cuda_runtime.h>
#include <cuda_bf16.h>
#include <cstdint>
#include <math.h>

#define NN 6144
#define NFEAT 512
#define NHID 256
#define NCLASS 8
#define ADIM 128

// ---------------- scratch (device globals; no allocation allowed) ----------
__device__ uint16_t g_adjH[(size_t)NN * NN];  // combined adjacency, bf16 hi
__device__ uint16_t g_adjL[(size_t)NN * NN];  // bf16 lo residual
__device__ uint16_t g_PH[(size_t)NN * NN];    // normalized attention, packed
__device__ uint16_t g_PL[(size_t)NN * NN];
__device__ float g_S[(size_t)NN * NN];        // raw scores Q@K^T (fp32)
__device__ float g_nz[NN * 3];
__device__ float g_Wc[NN * 16];
__device__ float g_bc[3];
__device__ float g_XW1[NN * NHID];
__device__ float g_x[NN * NHID];
__device__ float g_Q[NN * NHID];
__device__ float g_Kh[NN * NHID];
__device__ float g_V[NN * NHID];
__device__ float g_Xt[NN * NHID];
__device__ float g_XW2[NN * NCLASS];
// packed bf16 hi/lo operand buffers
__device__ uint16_t g_featH[(size_t)NN * NFEAT], g_featL[(size_t)NN * NFEAT];
__device__ uint16_t g_xH[NN * NHID],   g_xL[NN * NHID];
__device__ uint16_t g_QH[NN * NHID],   g_QL[NN * NHID];
__device__ uint16_t g_KH[NN * NHID],   g_KL[NN * NHID];
__device__ uint16_t g_VTH[NHID * NN],  g_VTL[NHID * NN];
__device__ uint16_t g_XW1TH[NHID * NN], g_XW1TL[NHID * NN];
__device__ uint16_t g_W1TH[NHID * NFEAT], g_W1TL[NHID * NFEAT];
__device__ uint16_t g_WqTH[NHID * NHID], g_WqTL[NHID * NHID];
__device__ uint16_t g_WkTH[NHID * NHID], g_WkTL[NHID * NHID];
__device__ uint16_t g_WvTH[NHID * NHID], g_WvTL[NHID * NHID];

// ================= helpers ==================================================
__device__ __forceinline__ uint32_t smem_to_u32(const void* p) {
    uint32_t a;
    asm("{ .reg .u64 t; cvta.to.shared.u64 t, %1; cvt.u32.u64 %0, t; }" : "=r"(a) : "l"(p));
    return a;
}

// split fp32 x4 -> bf16 hi pair + lo pair (lo = exact residual, re-rounded)
__device__ __forceinline__ void split4(float4 v, uint2& hi, uint2& lo) {
    uint32_t h0, h1, l0, l1;
    asm("cvt.rn.bf16x2.f32 %0, %1, %2;" : "=r"(h0) : "f"(v.y), "f"(v.x));
    asm("cvt.rn.bf16x2.f32 %0, %1, %2;" : "=r"(h1) : "f"(v.w), "f"(v.z));
    float r0 = v.x - __uint_as_float(h0 << 16);
    float r1 = v.y - __uint_as_float(h0 & 0xffff0000u);
    float r2 = v.z - __uint_as_float(h1 << 16);
    float r3 = v.w - __uint_as_float(h1 & 0xffff0000u);
    asm("cvt.rn.bf16x2.f32 %0, %1, %2;" : "=r"(l0) : "f"(r1), "f"(r0));
    asm("cvt.rn.bf16x2.f32 %0, %1, %2;" : "=r"(l1) : "f"(r3), "f"(r2));
    hi.x = h0; hi.y = h1; lo.x = l0; lo.y = l1;
}
// reconstruct 2 fp32 from packed bf16x2 hi + lo words
__device__ __forceinline__ void recon2(uint32_t h, uint32_t l, float& a, float& b) {
    a = __uint_as_float(h << 16) + __uint_as_float(l << 16);
    b = __uint_as_float(h & 0xffff0000u) + __uint_as_float(l & 0xffff0000u);
}

#define LDSM4(R, ADDR) \
    asm volatile("ldmatrix.sync.aligned.m8n8.x4.shared.b16 {%0,%1,%2,%3}, [%4];" \
                 : "=r"((R)[0]), "=r"((R)[1]), "=r"((R)[2]), "=r"((R)[3]) : "r"(ADDR))

#define MMA16816(D, A, B) \
    asm volatile("mma.sync.aligned.m16n8k16.row.col.f32.bf16.bf16.f32 " \
                 "{%0,%1,%2,%3}, {%4,%5,%6,%7}, {%8,%9}, {%0,%1,%2,%3};" \
                 : "+f"((D)[0]), "+f"((D)[1]), "+f"((D)[2]), "+f"((D)[3]) \
                 : "r"((A)[0]), "r"((A)[1]), "r"((A)[2]), "r"((A)[3]), \
                   "r"((B)[0]), "r"((B)[1]))

#define CP16(dst_u32, src_ptr) \
    asm volatile("cp.async.cg.shared.global [%0], [%1], 16;" \
                 :: "r"(dst_u32), "l"(src_ptr) : "memory")
#define CP_COMMIT() asm volatile("cp.async.commit_group;" ::: "memory")
#define CP_WAIT0()  asm volatile("cp.async.wait_group 0;" ::: "memory")

// ========= bf16x3 mma.sync GEMM on PRE-PACKED hi/lo operands ================
// C[M,N] = A @ B^T with A,B given as separate bf16 hi and lo matrices [.,K].
// Loader = pure cp.async (no ALU). 128x128 tile, BK=32, double-buffered,
// ONE sync per chunk. EPI bit0 = +bias, bit1 = relu. blockIdx.z muxes.
#define RS 40
#define ARR_B ((uint32_t)(128 * RS * 2))   // 10240 B per smem array
#define STG_B (4u * ARR_B)
#define MMA_SMEM (2 * (int)STG_B)          // 81920 B

template<int EPI>
__global__ __launch_bounds__(256)
void mma_gemm_packed(const uint16_t* Ah0, const uint16_t* Ah1, const uint16_t* Ah2,
                     const uint16_t* Al0, const uint16_t* Al1, const uint16_t* Al2,
                     const uint16_t* Bh0, const uint16_t* Bh1, const uint16_t* Bh2,
                     const uint16_t* Bl0, const uint16_t* Bl1, const uint16_t* Bl2,
                     const float* bi0, const float* bi1, const float* bi2,
                     float* C0, float* C1, float* C2, int ldc, int K)
{
    extern __shared__ uint8_t sm8[];
    const uint32_t sbase = smem_to_u32(sm8);

    const int z = blockIdx.z;
    const size_t aoff = (size_t)blockIdx.x * 128 * K;
    const size_t boff = (size_t)blockIdx.y * 128 * K;
    const uint16_t* Ah = (z == 0 ? Ah0 : (z == 1 ? Ah1 : Ah2)) + aoff;
    const uint16_t* Al = (z == 0 ? Al0 : (z == 1 ? Al1 : Al2)) + aoff;
    const uint16_t* Bh = (z == 0 ? Bh0 : (z == 1 ? Bh1 : Bh2)) + boff;
    const uint16_t* Bl = (z == 0 ? Bl0 : (z == 1 ? Bl1 : Bl2)) + boff;
    const float* bias = (z == 0 ? bi0 : (z == 1 ? bi1 : bi2));
    float* C = (z == 0 ? C0 : (z == 1 ? C1 : C2))
               + (size_t)blockIdx.x * 128 * ldc + (size_t)blockIdx.y * 128;

    const int tid = threadIdx.x, lane = tid & 31, wid = tid >> 5;
    const int wm = wid & 1, wn = wid >> 1;

    float acc[4][4][4];
#pragma unroll
    for (int a = 0; a < 4; a++)
#pragma unroll
        for (int b = 0; b < 4; b++)
#pragma unroll
            for (int c = 0; c < 4; c++) acc[a][b][c] = 0.f;

    const int nchunk = K >> 5;

    // ---- prologue: async-load chunk 0 into stage 0 ----
    {
        const uint32_t st = sbase;
#pragma unroll
        for (int i = 0; i < 2; i++) {
            int e = tid + i * 256;
            int r = e >> 2, g = e & 3;
            uint32_t so = st + (uint32_t)(r * RS + g * 8) * 2;
            size_t go = (size_t)r * K + g * 8;
            CP16(so,              Ah + go);
            CP16(so + ARR_B,      Al + go);
            CP16(so + 2 * ARR_B,  Bh + go);
            CP16(so + 3 * ARR_B,  Bl + go);
        }
        CP_COMMIT();
        CP_WAIT0();
    }
    __syncthreads();

    for (int kc = 0; kc < nchunk; kc++) {
        const int s = kc & 1;
        // ---- async-load next chunk into the other stage ----
        if (kc + 1 < nchunk) {
            const int k0n = (kc + 1) << 5;
            const uint32_t st = sbase + (uint32_t)(s ^ 1) * STG_B;
#pragma unroll
            for (int i = 0; i < 2; i++) {
                int e = tid + i * 256;
                int r = e >> 2, g = e & 3;
                uint32_t so = st + (uint32_t)(r * RS + g * 8) * 2;
                size_t go = (size_t)r * K + k0n + g * 8;
                CP16(so,              Ah + go);
                CP16(so + ARR_B,      Al + go);
                CP16(so + 2 * ARR_B,  Bh + go);
                CP16(so + 3 * ARR_B,  Bl + go);
            }
            CP_COMMIT();
        }
        // ---- MMAs on stage s ----
        const uint32_t st = sbase + (uint32_t)s * STG_B;
#pragma unroll
        for (int ks = 0; ks < 2; ks++) {
            const int k0 = ks * 16;
            uint32_t ah[4][4], al[4][4], bh[4][2], bl[4][2];
            const uint32_t a_addr = st +
                (uint32_t)(((wm * 64 + (lane & 15)) * RS + k0 + ((lane >> 4) << 3)) * 2);
#pragma unroll
            for (int mt = 0; mt < 4; mt++) {
                LDSM4(ah[mt], a_addr + (uint32_t)(mt * 16 * RS * 2));
                LDSM4(al[mt], a_addr + ARR_B + (uint32_t)(mt * 16 * RS * 2));
            }
            const uint32_t b_addr = st + 2u * ARR_B +
                (uint32_t)(((wn * 32 + (lane & 7) + ((lane >> 4) << 3)) * RS
                            + k0 + (((lane >> 3) & 1) << 3)) * 2);
            {
                uint32_t t[4];
                LDSM4(t, b_addr);
                bh[0][0] = t[0]; bh[0][1] = t[1]; bh[1][0] = t[2]; bh[1][1] = t[3];
                LDSM4(t, b_addr + (uint32_t)(16 * RS * 2));
                bh[2][0] = t[0]; bh[2][1] = t[1]; bh[3][0] = t[2]; bh[3][1] = t[3];
                LDSM4(t, b_addr + ARR_B);
                bl[0][0] = t[0]; bl[0][1] = t[1]; bl[1][0] = t[2]; bl[1][1] = t[3];
                LDSM4(t, b_addr + ARR_B + (uint32_t)(16 * RS * 2));
                bl[2][0] = t[0]; bl[2][1] = t[1]; bl[3][0] = t[2]; bl[3][1] = t[3];
            }
#pragma unroll
            for (int mt = 0; mt < 4; mt++)
#pragma unroll
                for (int nt = 0; nt < 4; nt++) {
                    MMA16816(acc[mt][nt], ah[mt], bh[nt]);
                    MMA16816(acc[mt][nt], ah[mt], bl[nt]);
                    MMA16816(acc[mt][nt], al[mt], bh[nt]);
                }
        }
        if (kc + 1 < nchunk) {
            CP_WAIT0();
            __syncthreads();
        }
    }

    // ---- epilogue ----
#pragma unroll
    for (int mt = 0; mt < 4; mt++) {
        int row0 = wm * 64 + mt * 16 + (lane >> 2);
#pragma unroll
        for (int nt = 0; nt < 4; nt++) {
            int col = wn * 32 + nt * 8 + (lane & 3) * 2;
            float b0 = 0.f, b1 = 0.f;
            if (EPI & 1) { b0 = bias[blockIdx.y * 128 + col]; b1 = bias[blockIdx.y * 128 + col + 1]; }
            float2 v0, v1;
            v0.x = acc[mt][nt][0] + b0; v0.y = acc[mt][nt][1] + b1;
            v1.x = acc[mt][nt][2] + b0; v1.y = acc[mt][nt][3] + b1;
            if (EPI & 2) {
                v0.x = fmaxf(v0.x, 0.f); v0.y = fmaxf(v0.y, 0.f);
                v1.x = fmaxf(v1.x, 0.f); v1.y = fmaxf(v1.y, 0.f);
            }
            *reinterpret_cast<float2*>(C + (size_t)row0 * ldc + col) = v0;
            *reinterpret_cast<float2*>(C + (size_t)(row0 + 8) * ldc + col) = v1;
        }
    }
}

// ================== pack fp32 -> bf16 hi/lo (flat) ==========================
__global__ __launch_bounds__(256)
void pack_kernel(const float* __restrict__ src, uint16_t* __restrict__ hi,
                 uint16_t* __restrict__ lo, int n8)
{
    int i = blockIdx.x * 256 + threadIdx.x;
    if (i >= n8) return;
    const float4* s4 = reinterpret_cast<const float4*>(src);
    float4 a = s4[i * 2], b = s4[i * 2 + 1];
    uint2 h0, l0, h1, l1;
    split4(a, h0, l0); split4(b, h1, l1);
    reinterpret_cast<uint4*>(hi)[i] = make_uint4(h0.x, h0.y, h1.x, h1.y);
    reinterpret_cast<uint4*>(lo)[i] = make_uint4(l0.x, l0.y, l1.x, l1.y);
}

// ============== transpose fp32 [R,C] -> packed bf16 hi/lo [C,R] =============
__global__ __launch_bounds__(256)
void transpose_pack_kernel(const float* __restrict__ src,
                           uint16_t* __restrict__ hi, uint16_t* __restrict__ lo,
                           int R, int C)
{
    __shared__ float t[32][33];
    int c0 = blockIdx.x * 32, r0 = blockIdx.y * 32;
    int x = threadIdx.x & 31, y = threadIdx.x >> 5;  // 32 x 8
#pragma unroll
    for (int j = 0; j < 32; j += 8)
        t[y + j][x] = src[(size_t)(r0 + y + j) * C + c0 + x];
    __syncthreads();
    int tlin = threadIdx.x;
    if (tlin < 128) {
        int o = tlin >> 2, g = tlin & 3;   // out-row o, 8-col group g
        float4 va, vb;
        va.x = t[g * 8 + 0][o]; va.y = t[g * 8 + 1][o];
        va.z = t[g * 8 + 2][o]; va.w = t[g * 8 + 3][o];
        vb.x = t[g * 8 + 4][o]; vb.y = t[g * 8 + 5][o];
        vb.z = t[g * 8 + 6][o]; vb.w = t[g * 8 + 7][o];
        uint2 h0, l0, h1, l1;
        split4(va, h0, l0); split4(vb, h1, l1);
        size_t base = ((size_t)(c0 + o) * R + r0 + g * 8) / 8;  // uint4 index
        reinterpret_cast<uint4*>(hi)[base] = make_uint4(h0.x, h0.y, h1.x, h1.y);
        reinterpret_cast<uint4*>(lo)[base] = make_uint4(l0.x, l0.y, l1.x, l1.y);
    }
}

// ---------------- Wc = Wa_i @ Wagg_block_i  (+ combined bias) ---------------
__global__ __launch_bounds__(256)
void wc_kernel(const float* __restrict__ Wa1, const float* __restrict__ Wa2,
               const float* __restrict__ Wa3, const float* __restrict__ Wagg,
               const float* __restrict__ ba1, const float* __restrict__ ba2,
               const float* __restrict__ ba3, const float* __restrict__ bagg)
{
    int idx = blockIdx.x * 256 + threadIdx.x;
    if (idx < 3 * NN) {
        int i = idx / NN, c = idx % NN;
        const float* Wa = (i == 0) ? Wa1 : ((i == 1) ? Wa2 : Wa3);
        float a0 = 0.f, a1 = 0.f, a2 = 0.f;
#pragma unroll 4
        for (int a = 0; a < ADIM; a++) {
            float w = Wa[(size_t)c * ADIM + a];
            const float* wg = Wagg + (size_t)(i * ADIM + a) * 3;
            a0 = fmaf(w, wg[0], a0); a1 = fmaf(w, wg[1], a1); a2 = fmaf(w, wg[2], a2);
        }
        g_Wc[(size_t)c * 16 + i * 4 + 0] = a0;
        g_Wc[(size_t)c * 16 + i * 4 + 1] = a1;
        g_Wc[(size_t)c * 16 + i * 4 + 2] = a2;
        g_Wc[(size_t)c * 16 + i * 4 + 3] = 0.f;
    }
    if (blockIdx.x == 0 && threadIdx.x < 3) {
        int j = threadIdx.x;
        float b = bagg[j];
        for (int a = 0; a < ADIM; a++) {
            b = fmaf(ba1[a], Wagg[(size_t)a * 3 + j], b);
            b = fmaf(ba2[a], Wagg[(size_t)(ADIM + a) * 3 + j], b);
            b = fmaf(ba3[a], Wagg[(size_t)(2 * ADIM + a) * 3 + j], b);
        }
        g_bc[j] = b;
    }
}

// ---------------- z4 = Σ_i adj_i @ Wc_i + bc ; 3-way softmax -> nz ----------
__global__ __launch_bounds__(256)
void z4nz_kernel(const float* __restrict__ a0, const float* __restrict__ a1,
                 const float* __restrict__ a2, float* __restrict__ out_nz)
{
    __shared__ float red[8][12];
    int r0 = blockIdx.x * 4;
    int tid = threadIdx.x, warp = tid >> 5, lane = tid & 31;
    float acc[4][3];
#pragma unroll
    for (int rr = 0; rr < 4; rr++)
#pragma unroll
        for (int j = 0; j < 3; j++) acc[rr][j] = 0.f;

    for (int it = 0; it < NN / 4 / 256; it++) {
        int idx = tid + it * 256;
        const float4* wcp = reinterpret_cast<const float4*>(g_Wc + (size_t)idx * 64);
        float4 wc[16];
#pragma unroll
        for (int q = 0; q < 16; q++) wc[q] = wcp[q];
#pragma unroll
        for (int rr = 0; rr < 4; rr++) {
            float4 v0 = reinterpret_cast<const float4*>(a0 + (size_t)(r0 + rr) * NN)[idx];
            float4 v1 = reinterpret_cast<const float4*>(a1 + (size_t)(r0 + rr) * NN)[idx];
            float4 v2 = reinterpret_cast<const float4*>(a2 + (size_t)(r0 + rr) * NN)[idx];
            const float av[3][4] = {{v0.x, v0.y, v0.z, v0.w},
                                    {v1.x, v1.y, v1.z, v1.w},
                                    {v2.x, v2.y, v2.z, v2.w}};
#pragma unroll
            for (int cc = 0; cc < 4; cc++)
#pragma unroll
                for (int i = 0; i < 3; i++) {
                    float4 w = wc[cc * 4 + i];
                    float a = av[i][cc];
                    acc[rr][0] = fmaf(a, w.x, acc[rr][0]);
                    acc[rr][1] = fmaf(a, w.y, acc[rr][1]);
                    acc[rr][2] = fmaf(a, w.z, acc[rr][2]);
                }
        }
    }
#pragma unroll
    for (int rr = 0; rr < 4; rr++)
#pragma unroll
        for (int j = 0; j < 3; j++) {
            float v = acc[rr][j];
#pragma unroll
            for (int off = 16; off; off >>= 1) v += __shfl_xor_sync(0xffffffffu, v, off);
            if (lane == 0) red[warp][rr * 3 + j] = v;
        }
    __syncthreads();
    if (tid == 0) {
#pragma unroll
        for (int rr = 0; rr < 4; rr++) {
            float z0 = g_bc[0], z1 = g_bc[1], z2 = g_bc[2];
#pragma unroll
            for (int w = 0; w < 8; w++) {
                z0 += red[w][rr * 3 + 0]; z1 += red[w][rr * 3 + 1]; z2 += red[w][rr * 3 + 2];
            }
            float m = fmaxf(z0, fmaxf(z1, z2));
            float e0 = __expf(z0 - m), e1 = __expf(z1 - m), e2 = __expf(z2 - m);
            float inv = 1.f / (e0 + e1 + e2);
            int row = r0 + rr;
            g_nz[row * 3 + 0] = e0 * inv; g_nz[row * 3 + 1] = e1 * inv; g_nz[row * 3 + 2] = e2 * inv;
            if (out_nz) {
                out_nz[row * 3 + 0] = e0 * inv; out_nz[row * 3 + 1] = e1 * inv;
                out_nz[row * 3 + 2] = e2 * inv;
            }
        }
    }
}

// ------- adj[r,c] = Σ_i nz[c,i]*adj_i[r,c], written as packed bf16 hi/lo ----
__global__ __launch_bounds__(256)
void combine_adj_kernel(const float* __restrict__ a0,
                        const float* __restrict__ a1,
                        const float* __restrict__ a2)
{
    size_t i8 = (size_t)blockIdx.x * 256 + threadIdx.x;   // 8-elem group index
    int c0 = (int)((i8 * 8) % NN);
    const float4* p0 = reinterpret_cast<const float4*>(a0) + i8 * 2;
    const float4* p1 = reinterpret_cast<const float4*>(a1) + i8 * 2;
    const float4* p2 = reinterpret_cast<const float4*>(a2) + i8 * 2;
    float4 r[2];
#pragma unroll
    for (int h = 0; h < 2; h++) {
        float4 v0 = p0[h], v1 = p1[h], v2 = p2[h];
        int c = c0 + h * 4;
        r[h].x = g_nz[(c + 0) * 3] * v0.x + g_nz[(c + 0) * 3 + 1] * v1.x + g_nz[(c + 0) * 3 + 2] * v2.x;
        r[h].y = g_nz[(c + 1) * 3] * v0.y + g_nz[(c + 1) * 3 + 1] * v1.y + g_nz[(c + 1) * 3 + 2] * v2.y;
        r[h].z = g_nz[(c + 2) * 3] * v0.z + g_nz[(c + 2) * 3 + 1] * v1.z + g_nz[(c + 2) * 3 + 2] * v2.z;
        r[h].w = g_nz[(c + 3) * 3] * v0.w + g_nz[(c + 3) * 3 + 1] * v1.w + g_nz[(c + 3) * 3 + 2] * v2.w;
    }
    uint2 h0, l0, h1, l1;
    split4(r[0], h0, l0); split4(r[1], h1, l1);
    reinterpret_cast<uint4*>(g_adjH)[i8] = make_uint4(h0.x, h0.y, h1.x, h1.y);
    reinterpret_cast<uint4*>(g_adjL)[i8] = make_uint4(l0.x, l0.y, l1.x, l1.y);
}

// ------- attention = row-softmax(adj * S) -> packed bf16 hi/lo --------------
// (_gcn_norm of a row-softmax is identity to ~1e-9; skipped.)
__global__ __launch_bounds__(256)
void att_softmax_kernel()
{
    __shared__ float sv[NN];
    __shared__ float red[8];
    int row = blockIdx.x, tid = threadIdx.x;
    const uint4* ah = reinterpret_cast<const uint4*>(g_adjH + (size_t)row * NN);
    const uint4* al = reinterpret_cast<const uint4*>(g_adjL + (size_t)row * NN);
    const float4* s4 = reinterpret_cast<const float4*>(g_S + (size_t)row * NN);

    float m = -3.4e38f;
    for (int j8 = tid; j8 < NN / 8; j8 += 256) {
        uint4 H = ah[j8], L = al[j8];
        float4 sa = s4[j8 * 2], sb = s4[j8 * 2 + 1];
        float a0, a1; float v[8];
        recon2(H.x, L.x, a0, a1); v[0] = a0 * sa.x; v[1] = a1 * sa.y;
        recon2(H.y, L.y, a0, a1); v[2] = a0 * sa.z; v[3] = a1 * sa.w;
        recon2(H.z, L.z, a0, a1); v[4] = a0 * sb.x; v[5] = a1 * sb.y;
        recon2(H.w, L.w, a0, a1); v[6] = a0 * sb.z; v[7] = a1 * sb.w;
#pragma unroll
        for (int k = 0; k < 8; k++) { sv[j8 * 8 + k] = v[k]; m = fmaxf(m, v[k]); }
    }
#pragma unroll
    for (int off = 16; off; off >>= 1) m = fmaxf(m, __shfl_xor_sync(0xffffffffu, m, off));
    if ((tid & 31) == 0) red[tid >> 5] = m;
    __syncthreads();
    float M = -3.4e38f;
#pragma unroll
    for (int i = 0; i < 8; i++) M = fmaxf(M, red[i]);
    __syncthreads();

    float s = 0.f;
    for (int j = tid; j < NN; j += 256) {
        float e = __expf(sv[j] - M);
        sv[j] = e;
        s += e;
    }
#pragma unroll
    for (int off = 16; off; off >>= 1) s += __shfl_xor_sync(0xffffffffu, s, off);
    if ((tid & 31) == 0) red[tid >> 5] = s;
    __syncthreads();
    float S = 0.f;
#pragma unroll
    for (int i = 0; i < 8; i++) S += red[i];
    float inv = 1.f / S;

    uint4* ph = reinterpret_cast<uint4*>(g_PH + (size_t)row * NN);
    uint4* pl = reinterpret_cast<uint4*>(g_PL + (size_t)row * NN);
    for (int j8 = tid; j8 < NN / 8; j8 += 256) {
        float4 va = reinterpret_cast<const float4*>(sv)[j8 * 2];
        float4 vb = reinterpret_cast<const float4*>(sv)[j8 * 2 + 1];
        va.x *= inv; va.y *= inv; va.z *= inv; va.w *= inv;
        vb.x *= inv; vb.y *= inv; vb.z *= inv; vb.w *= inv;
        uint2 h0, l0, h1, l1;
        split4(va, h0, l0); split4(vb, h1, l1);
        ph[j8] = make_uint4(h0.x, h0.y, h1.x, h1.y);
        pl[j8] = make_uint4(l0.x, l0.y, l1.x, l1.y);
    }
}

// ---------------- XW2 = X_tilde @ W2  (N=8) ---------------------------------
__global__ __launch_bounds__(256)
void xw2_kernel(const float* __restrict__ W2)
{
    __shared__ float sW[NHID][9];
    int tid = threadIdx.x;
    for (int i = tid; i < NHID * NCLASS; i += 256) sW[i / 8][i % 8] = W2[i];
    __syncthreads();
    int warp = tid >> 5, lane = tid & 31;
    int row = blockIdx.x * 8 + warp;
    const float* xr = g_Xt + (size_t)row * NHID;
    float acc[8] = {0, 0, 0, 0, 0, 0, 0, 0};
#pragma unroll
    for (int it = 0; it < NHID / 32; it++) {
        int k = it * 32 + lane;
        float xv = xr[k];
#pragma unroll
        for (int j = 0; j < 8; j++) acc[j] = fmaf(xv, sW[k][j], acc[j]);
    }
#pragma unroll
    for (int j = 0; j < 8; j++)
#pragma unroll
        for (int off = 16; off; off >>= 1)
            acc[j] += __shfl_xor_sync(0xffffffffu, acc[j], off);
    if (lane == 0) {
#pragma unroll
        for (int j = 0; j < 8; j++) g_XW2[(size_t)row * 8 + j] = acc[j];
    }
}

// ------- z = adj @ XW2 + b2 ; softmax rows -> out  (adj from packed) --------
__global__ __launch_bounds__(256)
void z_out_kernel(const float* __restrict__ b2, float* __restrict__ out)
{
    __shared__ float sW[512][9];
    int tid = threadIdx.x, warp = tid >> 5, lane = tid & 31;
    int row = blockIdx.x * 8 + warp;
    const uint16_t* ahr = g_adjH + (size_t)row * NN;
    const uint16_t* alr = g_adjL + (size_t)row * NN;
    float acc[8] = {0, 0, 0, 0, 0, 0, 0, 0};
    for (int c0 = 0; c0 < NN; c0 += 512) {
        __syncthreads();
        for (int i = tid; i < 512 * 8; i += 256) sW[i / 8][i % 8] = g_XW2[(size_t)(c0) * 8 + i];
        __syncthreads();
#pragma unroll
        for (int it = 0; it < 8; it++) {
            int k2 = it * 64 + lane * 2;
            uint32_t h = *reinterpret_cast<const uint32_t*>(ahr + c0 + k2);
            uint32_t l = *reinterpret_cast<const uint32_t*>(alr + c0 + k2);
            float a0, a1; recon2(h, l, a0, a1);
#pragma unroll
            for (int j = 0; j < 8; j++) {
                acc[j] = fmaf(a0, sW[k2][j], acc[j]);
                acc[j] = fmaf(a1, sW[k2 + 1][j], acc[j]);
            }
        }
    }
#pragma unroll
    for (int j = 0; j < 8; j++)
#pragma unroll
        for (int off = 16; off; off >>= 1)
            acc[j] += __shfl_xor_sync(0xffffffffu, acc[j], off);
    if (lane == 0) {
        float z[8]; float m = -3.4e38f;
#pragma unroll
        for (int j = 0; j < 8; j++) { z[j] = acc[j] + b2[j]; m = fmaxf(m, z[j]); }
        float s = 0.f;
#pragma unroll
        for (int j = 0; j < 8; j++) { z[j] = __expf(z[j] - m); s += z[j]; }
        float inv = 1.f / s;
#pragma unroll
        for (int j = 0; j < 8; j++) out[(size_t)row * 8 + j] = z[j] * inv;
    }
}

// ---------------- launch ----------------------------------------------------
extern "C" void kernel_launch(void* const* d_in, const int* in_sizes, int n_in,
                              void* d_out, int out_size)
{
    const float* adj0 = (const float*)d_in[0];
    const float* adj1 = (const float*)d_in[1];
    const float* adj2 = (const float*)d_in[2];
    const float* feat = (const float*)d_in[3];
    const float* Wa1  = (const float*)d_in[4];
    const float* ba1  = (const float*)d_in[5];
    const float* Wa2  = (const float*)d_in[6];
    const float* ba2  = (const float*)d_in[7];
    const float* Wa3  = (const float*)d_in[8];
    const float* ba3  = (const float*)d_in[9];
    const float* Wagg = (const float*)d_in[10];
    const float* bagg = (const float*)d_in[11];
    const float* W1   = (const float*)d_in[12];
    const float* b1   = (const float*)d_in[13];
    const float* Wq   = (const float*)d_in[14];
    const float* bq   = (const float*)d_in[15];
    const float* Wk   = (const float*)d_in[16];
    const float* bk   = (const float*)d_in[17];
    const float* Wv   = (const float*)d_in[18];
    const float* bv   = (const float*)d_in[19];
    const float* W2   = (const float*)d_in[20];
    const float* b2   = (const float*)d_in[21];
    float* out = (float*)d_out;

    float *S, *XW1, *x, *Q, *Kh, *V, *Xt;
    uint16_t *adjH, *adjL, *PH, *PL, *featH, *featL, *xH, *xL, *QH, *QL, *KHp, *KLp;
    uint16_t *VTH, *VTL, *XW1TH, *XW1TL, *W1TH, *W1TL;
    uint16_t *WqTH, *WqTL, *WkTH, *WkTL, *WvTH, *WvTL;
    cudaGetSymbolAddress((void**)&S,     g_S);
    cudaGetSymbolAddress((void**)&XW1,   g_XW1);
    cudaGetSymbolAddress((void**)&x,     g_x);
    cudaGetSymbolAddress((void**)&Q,     g_Q);
    cudaGetSymbolAddress((void**)&Kh,    g_Kh);
    cudaGetSymbolAddress((void**)&V,     g_V);
    cudaGetSymbolAddress((void**)&Xt,    g_Xt);
    cudaGetSymbolAddress((void**)&adjH,  g_adjH);
    cudaGetSymbolAddress((void**)&adjL,  g_adjL);
    cudaGetSymbolAddress((void**)&PH,    g_PH);
    cudaGetSymbolAddress((void**)&PL,    g_PL);
    cudaGetSymbolAddress((void**)&featH, g_featH);
    cudaGetSymbolAddress((void**)&featL, g_featL);
    cudaGetSymbolAddress((void**)&xH,    g_xH);
    cudaGetSymbolAddress((void**)&xL,    g_xL);
    cudaGetSymbolAddress((void**)&QH,    g_QH);
    cudaGetSymbolAddress((void**)&QL,    g_QL);
    cudaGetSymbolAddress((void**)&KHp,   g_KH);
    cudaGetSymbolAddress((void**)&KLp,   g_KL);
    cudaGetSymbolAddress((void**)&VTH,   g_VTH);
    cudaGetSymbolAddress((void**)&VTL,   g_VTL);
    cudaGetSymbolAddress((void**)&XW1TH, g_XW1TH);
    cudaGetSymbolAddress((void**)&XW1TL, g_XW1TL);
    cudaGetSymbolAddress((void**)&W1TH,  g_W1TH);
    cudaGetSymbolAddress((void**)&W1TL,  g_W1TL);
    cudaGetSymbolAddress((void**)&WqTH,  g_WqTH);
    cudaGetSymbolAddress((void**)&WqTL,  g_WqTL);
    cudaGetSymbolAddress((void**)&WkTH,  g_WkTH);
    cudaGetSymbolAddress((void**)&WkTL,  g_WkTL);
    cudaGetSymbolAddress((void**)&WvTH,  g_WvTH);
    cudaGetSymbolAddress((void**)&WvTL,  g_WvTL);

    cudaFuncSetAttribute(mma_gemm_packed<0>, cudaFuncAttributeMaxDynamicSharedMemorySize, MMA_SMEM);
    cudaFuncSetAttribute(mma_gemm_packed<1>, cudaFuncAttributeMaxDynamicSharedMemorySize, MMA_SMEM);
    cudaFuncSetAttribute(mma_gemm_packed<2>, cudaFuncAttributeMaxDynamicSharedMemorySize, MMA_SMEM);
    cudaFuncSetAttribute(mma_gemm_packed<3>, cudaFuncAttributeMaxDynamicSharedMemorySize, MMA_SMEM);

    // ---- operand preparation (packed bf16 hi/lo) ----
    transpose_pack_kernel<<<dim3(NHID / 32, NFEAT / 32), 256>>>(W1, W1TH, W1TL, NFEAT, NHID);
    transpose_pack_kernel<<<dim3(NHID / 32, NHID / 32), 256>>>(Wq, WqTH, WqTL, NHID, NHID);
    transpose_pack_kernel<<<dim3(NHID / 32, NHID / 32), 256>>>(Wk, WkTH, WkTL, NHID, NHID);
    transpose_pack_kernel<<<dim3(NHID / 32, NHID / 32), 256>>>(Wv, WvTH, WvTL, NHID, NHID);
    pack_kernel<<<(NN * NFEAT / 8 + 255) / 256, 256>>>(feat, featH, featL, NN * NFEAT / 8);

    // 1) Wc = Wa_i @ Wagg_block_i
    wc_kernel<<<(3 * NN + 255) / 256, 256>>>(Wa1, Wa2, Wa3, Wagg, ba1, ba2, ba3, bagg);

    // 2) z4 = Σ adj_i @ Wc_i + bc ; nz = softmax3
    float* out_nz = (out_size >= NN * (NCLASS + 3)) ? out + (size_t)NN * NCLASS : nullptr;
    z4nz_kernel<<<NN / 4, 256>>>(adj0, adj1, adj2, out_nz);

    // 3) adj = column-weighted combination -> packed bf16 hi/lo
    combine_adj_kernel<<<(int)((size_t)NN * NN / 8 / 256), 256>>>(adj0, adj1, adj2);

    // 4) XW1 = features @ W1
    mma_gemm_packed<0><<<dim3(NN / 128, NHID / 128, 1), 256, MMA_SMEM>>>(
        featH, featH, featH, featL, featL, featL,
        W1TH, W1TH, W1TH, W1TL, W1TL, W1TL,
        nullptr, nullptr, nullptr, XW1, XW1, XW1, NHID, NFEAT);
    transpose_pack_kernel<<<dim3(NHID / 32, NN / 32), 256>>>(XW1, XW1TH, XW1TL, NN, NHID);

    // 5) x = relu(adj @ XW1 + b1)
    mma_gemm_packed<3><<<dim3(NN / 128, NHID / 128, 1), 256, MMA_SMEM>>>(
        adjH, adjH, adjH, adjL, adjL, adjL,
        XW1TH, XW1TH, XW1TH, XW1TL, XW1TL, XW1TL,
        b1, b1, b1, x, x, x, NHID, NN);
    pack_kernel<<<(NN * NHID / 8 + 255) / 256, 256>>>(x, xH, xL, NN * NHID / 8);

    // 6) Q, K, V fused over blockIdx.z
    mma_gemm_packed<1><<<dim3(NN / 128, NHID / 128, 3), 256, MMA_SMEM>>>(
        xH, xH, xH, xL, xL, xL,
        WqTH, WkTH, WvTH, WqTL, WkTL, WvTL,
        bq, bk, bv, Q, Kh, V, NHID, NHID);
    pack_kernel<<<(NN * NHID / 8 + 255) / 256, 256>>>(Q, QH, QL, NN * NHID / 8);
    pack_kernel<<<(NN * NHID / 8 + 255) / 256, 256>>>(Kh, KHp, KLp, NN * NHID / 8);
    transpose_pack_kernel<<<dim3(NHID / 32, NN / 32), 256>>>(V, VTH, VTL, NN, NHID);

    // 7) S = Q @ K^T
    mma_gemm_packed<0><<<dim3(NN / 128, NN / 128, 1), 256, MMA_SMEM>>>(
        QH, QH, QH, QL, QL, QL,
        KHp, KHp, KHp, KLp, KLp, KLp,
        nullptr, nullptr, nullptr, S, S, S, NN, NHID);

    // 8) attention = row-softmax(adj * S) -> packed  (gcn_norm == identity)
    att_softmax_kernel<<<NN, 256>>>();

    // 9) X_tilde = relu(attention @ V)
    mma_gemm_packed<2><<<dim3(NN / 128, NHID / 128, 1), 256, MMA_SMEM>>>(
        PH, PH, PH, PL, PL, PL,
        VTH, VTH, VTH, VTL, VTL, VTL,
        nullptr, nullptr, nullptr, Xt, Xt, Xt, NHID, NN);

    // 10) XW2 = X_tilde @ W2
    xw2_kernel<<<NN / 8, 256>>>(W2);

    // 11) z = adj @ XW2 + b2 ; row softmax -> out[0 : N*8)
    z_out_kernel<<<NN / 8, 256>>>(b2, out);
}

// round 16
// speedup vs baseline: 1.1218x; 1.1218x over previous
#include <cuda_runtime.h>
#include <cuda_bf16.h>
#include <cstdint>
#include <math.h>

#define NN 6144
#define NFEAT 512
#define NHID 256
#define NCLASS 8
#define ADIM 128

// ---------------- scratch (device globals; no allocation allowed) ----------
__device__ float g_adj[(size_t)NN * NN];   // combined adjacency
__device__ float g_S[(size_t)NN * NN];     // scores -> attention (in-place)
__device__ float g_nz[NN * 3];
__device__ float g_Wc[NN * 16];            // fused Wa@Wagg, padded 16/row
__device__ float g_bc[3];
__device__ float g_XW1[NN * NHID];
__device__ float g_XW1T[NHID * NN];
__device__ float g_x[NN * NHID];
__device__ float g_Q[NN * NHID];
__device__ float g_Kh[NN * NHID];
__device__ float g_V[NN * NHID];
__device__ float g_VT[NHID * NN];
__device__ float g_Xt[NN * NHID];
__device__ float g_XW2[NN * NCLASS];
__device__ float g_W1T[NHID * NFEAT];
__device__ float g_WqT[NHID * NHID];
__device__ float g_WkT[NHID * NHID];
__device__ float g_WvT[NHID * NHID];

// ================= helpers ==================================================
__device__ __forceinline__ uint32_t smem_to_u32(const void* p) {
    uint32_t a;
    asm("{ .reg .u64 t; cvta.to.shared.u64 t, %1; cvt.u32.u64 %0, t; }" : "=r"(a) : "l"(p));
    return a;
}

// split fp32 x4 -> bf16 hi pair + lo pair (lo = exact residual, re-rounded)
__device__ __forceinline__ void split4(float4 v, uint2& hi, uint2& lo) {
    uint32_t h0, h1, l0, l1;
    asm("cvt.rn.bf16x2.f32 %0, %1, %2;" : "=r"(h0) : "f"(v.y), "f"(v.x));
    asm("cvt.rn.bf16x2.f32 %0, %1, %2;" : "=r"(h1) : "f"(v.w), "f"(v.z));
    float r0 = v.x - __uint_as_float(h0 << 16);
    float r1 = v.y - __uint_as_float(h0 & 0xffff0000u);
    float r2 = v.z - __uint_as_float(h1 << 16);
    float r3 = v.w - __uint_as_float(h1 & 0xffff0000u);
    asm("cvt.rn.bf16x2.f32 %0, %1, %2;" : "=r"(l0) : "f"(r1), "f"(r0));
    asm("cvt.rn.bf16x2.f32 %0, %1, %2;" : "=r"(l1) : "f"(r3), "f"(r2));
    hi.x = h0; hi.y = h1; lo.x = l0; lo.y = l1;
}

#define LDSM4(R, ADDR) \
    asm volatile("ldmatrix.sync.aligned.m8n8.x4.shared.b16 {%0,%1,%2,%3}, [%4];" \
                 : "=r"((R)[0]), "=r"((R)[1]), "=r"((R)[2]), "=r"((R)[3]) : "r"(ADDR))

#define MMA16816(D, A, B) \
    asm volatile("mma.sync.aligned.m16n8k16.row.col.f32.bf16.bf16.f32 " \
                 "{%0,%1,%2,%3}, {%4,%5,%6,%7}, {%8,%9}, {%0,%1,%2,%3};" \
                 : "+f"((D)[0]), "+f"((D)[1]), "+f"((D)[2]), "+f"((D)[3]) \
                 : "r"((A)[0]), "r"((A)[1]), "r"((A)[2]), "r"((A)[3]), \
                   "r"((B)[0]), "r"((B)[1]))

// ================== bf16x3 mma.sync GEMM: C[M,N] = A[M,K] @ B[N,K]^T ========
// fp32 in/out, split on the fly. 128x128 tile, BK=32, double-buffered smem.
// ONE barrier per chunk: the pre-convert sync is redundant (convert writes
// stage s^1, whose last readers were ordered by the previous chunk's sync;
// current MMA reads stage s only) — removing it lets fast warps convert
// while slow warps are still issuing HMMA.
// EPI bit0 = +bias[col], bit1 = relu. blockIdx.z selects {A,B,bias,C}.
#define RS 40                       // smem row stride (bf16) -> conflict-free
#define ARR_B ((uint32_t)(128 * RS * 2))   // 10240 bytes per array
#define STG_B (4u * ARR_B)                 // Ah, Al, Bh, Bl per stage
#define MMA_SMEM (2 * (int)STG_B)          // 81920 bytes

template<int EPI>
__global__ __launch_bounds__(256, 1)
void mma_gemm_kernel(const float* A0, const float* A1, const float* A2,
                     const float* B0, const float* B1, const float* B2,
                     const float* bi0, const float* bi1, const float* bi2,
                     float* C0, float* C1, float* C2,
                     int ldc, int K)
{
    extern __shared__ uint8_t sm8[];
    const uint32_t sbase = smem_to_u32(sm8);

    const int z = blockIdx.z;
    const float* A = (z == 0 ? A0 : (z == 1 ? A1 : A2)) + (size_t)blockIdx.x * 128 * K;
    const float* B = (z == 0 ? B0 : (z == 1 ? B1 : B2)) + (size_t)blockIdx.y * 128 * K;
    const float* bias = (z == 0 ? bi0 : (z == 1 ? bi1 : bi2));
    float* C = (z == 0 ? C0 : (z == 1 ? C1 : C2))
               + (size_t)blockIdx.x * 128 * ldc + (size_t)blockIdx.y * 128;

    const int tid = threadIdx.x, lane = tid & 31, wid = tid >> 5;
    const int wm = wid & 1;        // 2 M-slabs of 64
    const int wn = wid >> 1;       // 4 N-slabs of 32

    float acc[4][4][4];
#pragma unroll
    for (int a = 0; a < 4; a++)
#pragma unroll
        for (int b = 0; b < 4; b++)
#pragma unroll
            for (int c = 0; c < 4; c++) acc[a][b][c] = 0.f;

    const int nchunk = K >> 5;
    float4 ld[8];

    // ---- prologue: load + convert chunk 0 ----
#pragma unroll
    for (int i = 0; i < 8; i++) {
        int e = tid + i * 256;
        int r = (e & 1023) >> 3, c = e & 7;
        const float* src = (i < 4) ? A : B;
        ld[i] = *reinterpret_cast<const float4*>(src + (size_t)r * K + c * 4);
    }
#pragma unroll
    for (int i = 0; i < 8; i++) {
        int e = tid + i * 256;
        int r = (e & 1023) >> 3, c = e & 7;
        uint2 hi, lo; split4(ld[i], hi, lo);
        uint32_t off = (i < 4 ? 0u : 2u * ARR_B) + (uint32_t)(r * RS + c * 4) * 2u;
        *reinterpret_cast<uint2*>(sm8 + off) = hi;
        *reinterpret_cast<uint2*>(sm8 + off + ARR_B) = lo;
    }
    __syncthreads();

    for (int kc = 0; kc < nchunk; kc++) {
        const int s = kc & 1;
        // ---- issue next chunk's global loads (latency hidden by MMAs) ----
        if (kc + 1 < nchunk) {
            const int k0n = (kc + 1) << 5;
#pragma unroll
            for (int i = 0; i < 8; i++) {
                int e = tid + i * 256;
                int r = (e & 1023) >> 3, c = e & 7;
                const float* src = (i < 4) ? A : B;
                ld[i] = *reinterpret_cast<const float4*>(src + (size_t)r * K + k0n + c * 4);
            }
        }
        // ---- MMA on stage s ----
        const uint32_t st = sbase + (uint32_t)s * STG_B;
#pragma unroll
        for (int ks = 0; ks < 2; ks++) {
            const int k0 = ks * 16;
            uint32_t ah[4][4], al[4][4], bh[4][2], bl[4][2];
            const uint32_t a_addr = st +
                (uint32_t)(((wm * 64 + (lane & 15)) * RS + k0 + ((lane >> 4) << 3)) * 2);
#pragma unroll
            for (int mt = 0; mt < 4; mt++) {
                LDSM4(ah[mt], a_addr + (uint32_t)(mt * 16 * RS * 2));
                LDSM4(al[mt], a_addr + ARR_B + (uint32_t)(mt * 16 * RS * 2));
            }
            const uint32_t b_addr = st + 2u * ARR_B +
                (uint32_t)(((wn * 32 + (lane & 7) + ((lane >> 4) << 3)) * RS
                            + k0 + (((lane >> 3) & 1) << 3)) * 2);
            {
                uint32_t t[4];
                LDSM4(t, b_addr);
                bh[0][0] = t[0]; bh[0][1] = t[1]; bh[1][0] = t[2]; bh[1][1] = t[3];
                LDSM4(t, b_addr + (uint32_t)(16 * RS * 2));
                bh[2][0] = t[0]; bh[2][1] = t[1]; bh[3][0] = t[2]; bh[3][1] = t[3];
                LDSM4(t, b_addr + ARR_B);
                bl[0][0] = t[0]; bl[0][1] = t[1]; bl[1][0] = t[2]; bl[1][1] = t[3];
                LDSM4(t, b_addr + ARR_B + (uint32_t)(16 * RS * 2));
                bl[2][0] = t[0]; bl[2][1] = t[1]; bl[3][0] = t[2]; bl[3][1] = t[3];
            }
#pragma unroll
            for (int mt = 0; mt < 4; mt++)
#pragma unroll
                for (int nt = 0; nt < 4; nt++) {
                    MMA16816(acc[mt][nt], ah[mt], bh[nt]);   // hi*hi
                    MMA16816(acc[mt][nt], ah[mt], bl[nt]);   // hi*lo
                    MMA16816(acc[mt][nt], al[mt], bh[nt]);   // lo*hi
                }
        }
        // ---- convert next chunk into the other stage (no pre-sync:
        //      stage s^1's last readers were fenced by the previous barrier) ----
        if (kc + 1 < nchunk) {
            const uint32_t so = (uint32_t)(s ^ 1) * STG_B;
#pragma unroll
            for (int i = 0; i < 8; i++) {
                int e = tid + i * 256;
                int r = (e & 1023) >> 3, c = e & 7;
                uint2 hi, lo; split4(ld[i], hi, lo);
                uint32_t off = so + (i < 4 ? 0u : 2u * ARR_B)
                             + (uint32_t)(r * RS + c * 4) * 2u;
                *reinterpret_cast<uint2*>(sm8 + off) = hi;
                *reinterpret_cast<uint2*>(sm8 + off + ARR_B) = lo;
            }
            __syncthreads();
        }
    }

    // ---- epilogue: c-frag -> gmem (float2 stores), bias/relu ----
#pragma unroll
    for (int mt = 0; mt < 4; mt++) {
        int row0 = wm * 64 + mt * 16 + (lane >> 2);
#pragma unroll
        for (int nt = 0; nt < 4; nt++) {
            int col = wn * 32 + nt * 8 + (lane & 3) * 2;
            float b0 = 0.f, b1 = 0.f;
            if (EPI & 1) { b0 = bias[blockIdx.y * 128 + col]; b1 = bias[blockIdx.y * 128 + col + 1]; }
            float2 v0, v1;
            v0.x = acc[mt][nt][0] + b0; v0.y = acc[mt][nt][1] + b1;
            v1.x = acc[mt][nt][2] + b0; v1.y = acc[mt][nt][3] + b1;
            if (EPI & 2) {
                v0.x = fmaxf(v0.x, 0.f); v0.y = fmaxf(v0.y, 0.f);
                v1.x = fmaxf(v1.x, 0.f); v1.y = fmaxf(v1.y, 0.f);
            }
            *reinterpret_cast<float2*>(C + (size_t)row0 * ldc + col) = v0;
            *reinterpret_cast<float2*>(C + (size_t)(row0 + 8) * ldc + col) = v1;
        }
    }
}

// ================== transpose fp32 [R,C] -> [C,R] ===========================
__global__ __launch_bounds__(256)
void transpose_kernel(const float* __restrict__ src, float* __restrict__ dst, int R, int C)
{
    __shared__ float t[32][33];
    int c0 = blockIdx.x * 32, r0 = blockIdx.y * 32;
    int x = threadIdx.x, y = threadIdx.y;  // 32 x 8
#pragma unroll
    for (int j = 0; j < 32; j += 8)
        t[y + j][x] = src[(size_t)(r0 + y + j) * C + c0 + x];
    __syncthreads();
#pragma unroll
    for (int j = 0; j < 32; j += 8)
        dst[(size_t)(c0 + y + j) * R + r0 + x] = t[x][y + j];
}

// ---------------- Wc = Wa_i @ Wagg_block_i  (+ combined bias) ---------------
__global__ __launch_bounds__(256)
void wc_kernel(const float* __restrict__ Wa1, const float* __restrict__ Wa2,
               const float* __restrict__ Wa3, const float* __restrict__ Wagg,
               const float* __restrict__ ba1, const float* __restrict__ ba2,
               const float* __restrict__ ba3, const float* __restrict__ bagg)
{
    int idx = blockIdx.x * 256 + threadIdx.x;   // 3*NN threads
    if (idx < 3 * NN) {
        int i = idx / NN, c = idx % NN;
        const float* Wa = (i == 0) ? Wa1 : ((i == 1) ? Wa2 : Wa3);
        float a0 = 0.f, a1 = 0.f, a2 = 0.f;
#pragma unroll 4
        for (int a = 0; a < ADIM; a++) {
            float w = Wa[(size_t)c * ADIM + a];
            const float* wg = Wagg + (size_t)(i * ADIM + a) * 3;
            a0 = fmaf(w, wg[0], a0); a1 = fmaf(w, wg[1], a1); a2 = fmaf(w, wg[2], a2);
        }
        g_Wc[(size_t)c * 16 + i * 4 + 0] = a0;
        g_Wc[(size_t)c * 16 + i * 4 + 1] = a1;
        g_Wc[(size_t)c * 16 + i * 4 + 2] = a2;
        g_Wc[(size_t)c * 16 + i * 4 + 3] = 0.f;
    }
    if (blockIdx.x == 0 && threadIdx.x < 3) {
        int j = threadIdx.x;
        float b = bagg[j];
        for (int a = 0; a < ADIM; a++) {
            b = fmaf(ba1[a], Wagg[(size_t)a * 3 + j], b);
            b = fmaf(ba2[a], Wagg[(size_t)(ADIM + a) * 3 + j], b);
            b = fmaf(ba3[a], Wagg[(size_t)(2 * ADIM + a) * 3 + j], b);
        }
        g_bc[j] = b;
    }
}

// ---------------- z4 = Σ_i adj_i @ Wc_i + bc ; 3-way softmax -> nz ----------
__global__ __launch_bounds__(256)
void z4nz_kernel(const float* __restrict__ a0, const float* __restrict__ a1,
                 const float* __restrict__ a2, float* __restrict__ out_nz)
{
    __shared__ float red[8][12];
    int r0 = blockIdx.x * 4;
    int tid = threadIdx.x, warp = tid >> 5, lane = tid & 31;
    float acc[4][3];
#pragma unroll
    for (int rr = 0; rr < 4; rr++)
#pragma unroll
        for (int j = 0; j < 3; j++) acc[rr][j] = 0.f;

    for (int it = 0; it < NN / 4 / 256; it++) {
        int idx = tid + it * 256;            // float4 index along columns
        const float4* wcp = reinterpret_cast<const float4*>(g_Wc + (size_t)idx * 64);
        float4 wc[16];
#pragma unroll
        for (int q = 0; q < 16; q++) wc[q] = wcp[q];
#pragma unroll
        for (int rr = 0; rr < 4; rr++) {
            float4 v0 = reinterpret_cast<const float4*>(a0 + (size_t)(r0 + rr) * NN)[idx];
            float4 v1 = reinterpret_cast<const float4*>(a1 + (size_t)(r0 + rr) * NN)[idx];
            float4 v2 = reinterpret_cast<const float4*>(a2 + (size_t)(r0 + rr) * NN)[idx];
            const float av[3][4] = {{v0.x, v0.y, v0.z, v0.w},
                                    {v1.x, v1.y, v1.z, v1.w},
                                    {v2.x, v2.y, v2.z, v2.w}};
#pragma unroll
            for (int cc = 0; cc < 4; cc++)
#pragma unroll
                for (int i = 0; i < 3; i++) {
                    float4 w = wc[cc * 4 + i];
                    float a = av[i][cc];
                    acc[rr][0] = fmaf(a, w.x, acc[rr][0]);
                    acc[rr][1] = fmaf(a, w.y, acc[rr][1]);
                    acc[rr][2] = fmaf(a, w.z, acc[rr][2]);
                }
        }
    }
#pragma unroll
    for (int rr = 0; rr < 4; rr++)
#pragma unroll
        for (int j = 0; j < 3; j++) {
            float v = acc[rr][j];
#pragma unroll
            for (int off = 16; off; off >>= 1) v += __shfl_xor_sync(0xffffffffu, v, off);
            if (lane == 0) red[warp][rr * 3 + j] = v;
        }
    __syncthreads();
    if (tid == 0) {
#pragma unroll
        for (int rr = 0; rr < 4; rr++) {
            float z0 = g_bc[0], z1 = g_bc[1], z2 = g_bc[2];
#pragma unroll
            for (int w = 0; w < 8; w++) {
                z0 += red[w][rr * 3 + 0]; z1 += red[w][rr * 3 + 1]; z2 += red[w][rr * 3 + 2];
            }
            float m = fmaxf(z0, fmaxf(z1, z2));
            float e0 = __expf(z0 - m), e1 = __expf(z1 - m), e2 = __expf(z2 - m);
            float inv = 1.f / (e0 + e1 + e2);
            int row = r0 + rr;
            g_nz[row * 3 + 0] = e0 * inv; g_nz[row * 3 + 1] = e1 * inv; g_nz[row * 3 + 2] = e2 * inv;
            if (out_nz) {
                out_nz[row * 3 + 0] = e0 * inv; out_nz[row * 3 + 1] = e1 * inv;
                out_nz[row * 3 + 2] = e2 * inv;
            }
        }
    }
}

// ---------------- adj[r,c] = sum_i nz[c,i] * adj_i[r,c] ---------------------
__global__ __launch_bounds__(256)
void combine_adj_kernel(const float* __restrict__ a0,
                        const float* __restrict__ a1,
                        const float* __restrict__ a2)
{
    size_t idx = (size_t)blockIdx.x * 256 + threadIdx.x;   // float4 index
    int c = (int)(idx % (NN / 4)) * 4;
    float4 v0 = ((const float4*)a0)[idx];
    float4 v1 = ((const float4*)a1)[idx];
    float4 v2 = ((const float4*)a2)[idx];
    float4 r;
    r.x = g_nz[(c + 0) * 3] * v0.x + g_nz[(c + 0) * 3 + 1] * v1.x + g_nz[(c + 0) * 3 + 2] * v2.x;
    r.y = g_nz[(c + 1) * 3] * v0.y + g_nz[(c + 1) * 3 + 1] * v1.y + g_nz[(c + 1) * 3 + 2] * v2.y;
    r.z = g_nz[(c + 2) * 3] * v0.z + g_nz[(c + 2) * 3 + 1] * v1.z + g_nz[(c + 2) * 3 + 2] * v2.z;
    r.w = g_nz[(c + 3) * 3] * v0.w + g_nz[(c + 3) * 3 + 1] * v1.w + g_nz[(c + 3) * 3 + 2] * v2.w;
    ((float4*)g_adj)[idx] = r;
}

// ---------------- attention = row-softmax(adj * S), in place ----------------
// (_gcn_norm of a row-softmax is identity to ~1e-9; skipped.)
__global__ __launch_bounds__(256)
void att_softmax_kernel()
{
    __shared__ float sv[NN];
    __shared__ float red[8];
    int row = blockIdx.x, tid = threadIdx.x;
    const float* ar = g_adj + (size_t)row * NN;
    float* sr = g_S + (size_t)row * NN;

    float m = -3.4e38f;
    for (int j = tid; j < NN; j += 256) {
        float v = ar[j] * sr[j];
        sv[j] = v;
        m = fmaxf(m, v);
    }
#pragma unroll
    for (int off = 16; off; off >>= 1) m = fmaxf(m, __shfl_xor_sync(0xffffffffu, m, off));
    if ((tid & 31) == 0) red[tid >> 5] = m;
    __syncthreads();
    float M = -3.4e38f;
#pragma unroll
    for (int i = 0; i < 8; i++) M = fmaxf(M, red[i]);
    __syncthreads();

    float s = 0.f;
    for (int j = tid; j < NN; j += 256) {
        float e = __expf(sv[j] - M);
        sv[j] = e;
        s += e;
    }
#pragma unroll
    for (int off = 16; off; off >>= 1) s += __shfl_xor_sync(0xffffffffu, s, off);
    if ((tid & 31) == 0) red[tid >> 5] = s;
    __syncthreads();
    float S = 0.f;
#pragma unroll
    for (int i = 0; i < 8; i++) S += red[i];
    float inv = 1.f / S;

    for (int j = tid; j < NN; j += 256) sr[j] = sv[j] * inv;
}

// ---------------- XW2 = X_tilde @ W2  (N=8) ---------------------------------
__global__ __launch_bounds__(256)
void xw2_kernel(const float* __restrict__ W2)
{
    __shared__ float sW[NHID][9];
    int tid = threadIdx.x;
    for (int i = tid; i < NHID * NCLASS; i += 256) sW[i / 8][i % 8] = W2[i];
    __syncthreads();
    int warp = tid >> 5, lane = tid & 31;
    int row = blockIdx.x * 8 + warp;
    const float* xr = g_Xt + (size_t)row * NHID;
    float acc[8] = {0, 0, 0, 0, 0, 0, 0, 0};
#pragma unroll
    for (int it = 0; it < NHID / 32; it++) {
        int k = it * 32 + lane;
        float xv = xr[k];
#pragma unroll
        for (int j = 0; j < 8; j++) acc[j] = fmaf(xv, sW[k][j], acc[j]);
    }
#pragma unroll
    for (int j = 0; j < 8; j++)
#pragma unroll
        for (int off = 16; off; off >>= 1)
            acc[j] += __shfl_xor_sync(0xffffffffu, acc[j], off);
    if (lane == 0) {
#pragma unroll
        for (int j = 0; j < 8; j++) g_XW2[(size_t)row * 8 + j] = acc[j];
    }
}

// ---------------- z = adj @ XW2 + b2 ; softmax rows -> out ------------------
__global__ __launch_bounds__(256)
void z_out_kernel(const float* __restrict__ b2, float* __restrict__ out)
{
    __shared__ float sW[512][9];
    int tid = threadIdx.x, warp = tid >> 5, lane = tid & 31;
    int row = blockIdx.x * 8 + warp;
    const float* ar = g_adj + (size_t)row * NN;
    float acc[8] = {0, 0, 0, 0, 0, 0, 0, 0};
    for (int c0 = 0; c0 < NN; c0 += 512) {
        __syncthreads();
        for (int i = tid; i < 512 * 8; i += 256) sW[i / 8][i % 8] = g_XW2[(size_t)(c0) * 8 + i];
        __syncthreads();
#pragma unroll
        for (int it = 0; it < 16; it++) {
            int k = it * 32 + lane;
            float a = ar[c0 + k];
#pragma unroll
            for (int j = 0; j < 8; j++) acc[j] = fmaf(a, sW[k][j], acc[j]);
        }
    }
#pragma unroll
    for (int j = 0; j < 8; j++)
#pragma unroll
        for (int off = 16; off; off >>= 1)
            acc[j] += __shfl_xor_sync(0xffffffffu, acc[j], off);
    if (lane == 0) {
        float z[8]; float m = -3.4e38f;
#pragma unroll
        for (int j = 0; j < 8; j++) { z[j] = acc[j] + b2[j]; m = fmaxf(m, z[j]); }
        float s = 0.f;
#pragma unroll
        for (int j = 0; j < 8; j++) { z[j] = __expf(z[j] - m); s += z[j]; }
        float inv = 1.f / s;
#pragma unroll
        for (int j = 0; j < 8; j++) out[(size_t)row * 8 + j] = z[j] * inv;
    }
}

// ---------------- launch ----------------------------------------------------
extern "C" void kernel_launch(void* const* d_in, const int* in_sizes, int n_in,
                              void* d_out, int out_size)
{
    const float* adj0 = (const float*)d_in[0];
    const float* adj1 = (const float*)d_in[1];
    const float* adj2 = (const float*)d_in[2];
    const float* feat = (const float*)d_in[3];
    const float* Wa1  = (const float*)d_in[4];
    const float* ba1  = (const float*)d_in[5];
    const float* Wa2  = (const float*)d_in[6];
    const float* ba2  = (const float*)d_in[7];
    const float* Wa3  = (const float*)d_in[8];
    const float* ba3  = (const float*)d_in[9];
    const float* Wagg = (const float*)d_in[10];
    const float* bagg = (const float*)d_in[11];
    const float* W1   = (const float*)d_in[12];
    const float* b1   = (const float*)d_in[13];
    const float* Wq   = (const float*)d_in[14];
    const float* bq   = (const float*)d_in[15];
    const float* Wk   = (const float*)d_in[16];
    const float* bk   = (const float*)d_in[17];
    const float* Wv   = (const float*)d_in[18];
    const float* bv   = (const float*)d_in[19];
    const float* W2   = (const float*)d_in[20];
    const float* b2   = (const float*)d_in[21];
    float* out = (float*)d_out;

    float *adjC, *S, *XW1, *XW1T, *x, *Q, *Kh, *V, *VT, *Xt;
    float *W1T, *WqT, *WkT, *WvT;
    cudaGetSymbolAddress((void**)&adjC, g_adj);
    cudaGetSymbolAddress((void**)&S,    g_S);
    cudaGetSymbolAddress((void**)&XW1,  g_XW1);
    cudaGetSymbolAddress((void**)&XW1T, g_XW1T);
    cudaGetSymbolAddress((void**)&x,    g_x);
    cudaGetSymbolAddress((void**)&Q,    g_Q);
    cudaGetSymbolAddress((void**)&Kh,   g_Kh);
    cudaGetSymbolAddress((void**)&V,    g_V);
    cudaGetSymbolAddress((void**)&VT,   g_VT);
    cudaGetSymbolAddress((void**)&Xt,   g_Xt);
    cudaGetSymbolAddress((void**)&W1T,  g_W1T);
    cudaGetSymbolAddress((void**)&WqT,  g_WqT);
    cudaGetSymbolAddress((void**)&WkT,  g_WkT);
    cudaGetSymbolAddress((void**)&WvT,  g_WvT);

    cudaFuncSetAttribute(mma_gemm_kernel<0>, cudaFuncAttributeMaxDynamicSharedMemorySize, MMA_SMEM);
    cudaFuncSetAttribute(mma_gemm_kernel<1>, cudaFuncAttributeMaxDynamicSharedMemorySize, MMA_SMEM);
    cudaFuncSetAttribute(mma_gemm_kernel<2>, cudaFuncAttributeMaxDynamicSharedMemorySize, MMA_SMEM);
    cudaFuncSetAttribute(mma_gemm_kernel<3>, cudaFuncAttributeMaxDynamicSharedMemorySize, MMA_SMEM);

    dim3 tb(32, 8);
    // small weight transposes ([K,N] -> [N,K] for the MMA B operand)
    transpose_kernel<<<dim3(NHID / 32, NFEAT / 32), tb>>>(W1, W1T, NFEAT, NHID);
    transpose_kernel<<<dim3(NHID / 32, NHID / 32), tb>>>(Wq, WqT, NHID, NHID);
    transpose_kernel<<<dim3(NHID / 32, NHID / 32), tb>>>(Wk, WkT, NHID, NHID);
    transpose_kernel<<<dim3(NHID / 32, NHID / 32), tb>>>(Wv, WvT, NHID, NHID);

    // 1) Wc = Wa_i @ Wagg_block_i  (tiny; replaces the 87-GF z-GEMM)
    wc_kernel<<<(3 * NN + 255) / 256, 256>>>(Wa1, Wa2, Wa3, Wagg, ba1, ba2, ba3, bagg);

    // 2) z4 = Σ adj_i @ Wc_i + bc ; nz = softmax3 (bandwidth pass, fp32-exact)
    float* out_nz = (out_size >= NN * (NCLASS + 3)) ? out + (size_t)NN * NCLASS : nullptr;
    z4nz_kernel<<<NN / 4, 256>>>(adj0, adj1, adj2, out_nz);

    // 3) adj = column-weighted combination
    combine_adj_kernel<<<(NN / 4) * (NN / 256), 256>>>(adj0, adj1, adj2);

    // 4) XW1 = features @ W1
    mma_gemm_kernel<0><<<dim3(NN / 128, NHID / 128, 1), 256, MMA_SMEM>>>(
        feat, feat, feat, W1T, W1T, W1T, nullptr, nullptr, nullptr,
        XW1, XW1, XW1, NHID, NFEAT);
    transpose_kernel<<<dim3(NHID / 32, NN / 32), tb>>>(XW1, XW1T, NN, NHID);

    // 5) x = relu(adj @ XW1 + b1)
    mma_gemm_kernel<3><<<dim3(NN / 128, NHID / 128, 1), 256, MMA_SMEM>>>(
        adjC, adjC, adjC, XW1T, XW1T, XW1T, b1, b1, b1,
        x, x, x, NHID, NN);

    // 6) Q, K, V fused over blockIdx.z
    mma_gemm_kernel<1><<<dim3(NN / 128, NHID / 128, 3), 256, MMA_SMEM>>>(
        x, x, x, WqT, WkT, WvT, bq, bk, bv,
        Q, Kh, V, NHID, NHID);
    transpose_kernel<<<dim3(NHID / 32, NN / 32), tb>>>(V, VT, NN, NHID);

    // 7) S = Q @ K^T   (K_h is already [N,K] for the B operand)
    mma_gemm_kernel<0><<<dim3(NN / 128, NN / 128, 1), 256, MMA_SMEM>>>(
        Q, Q, Q, Kh, Kh, Kh, nullptr, nullptr, nullptr,
        S, S, S, NN, NHID);

    // 8) attention = row-softmax(adj * S)   (gcn_norm == identity, skipped)
    att_softmax_kernel<<<NN, 256>>>();

    // 9) X_tilde = relu(attention @ V)
    mma_gemm_kernel<2><<<dim3(NN / 128, NHID / 128, 1), 256, MMA_SMEM>>>(
        S, S, S, VT, VT, VT, nullptr, nullptr, nullptr,
        Xt, Xt, Xt, NHID, NN);

    // 10) XW2 = X_tilde @ W2
    xw2_kernel<<<NN / 8, 256>>>(W2);

    // 11) z = adj @ XW2 + b2 ; row softmax -> out[0 : N*8)
    z_out_kernel<<<NN / 8, 256>>>(b2, out);
}